// round 1
// baseline (speedup 1.0000x reference)
#include <cuda_runtime.h>
#include <math.h>

#define Bn    64
#define Nn    256
#define XDim  118
#define EDim  5
#define Hd    384
#define NHd   8
#define DHd   48
#define DFFd  1536
#define DEPTH 6
#define Mrows (Bn * Nn)            /* 16384 */
#define KCAT  (XDim + Nn * EDim)   /* 1398  */
#define EROW  (Nn * EDim)          /* 1280  */

// ---------------- scratch (device globals; no allocation) ----------------
__device__ float g_cat[(size_t)Mrows * KCAT];        // 22.9M
__device__ float g_z  [(size_t)Mrows * Hd];
__device__ float g_q  [(size_t)Mrows * Hd];
__device__ float g_k  [(size_t)Mrows * Hd];
__device__ float g_v  [(size_t)Mrows * Hd];
__device__ float g_y  [(size_t)Mrows * Hd];
__device__ float g_x1 [(size_t)Mrows * Hd];
__device__ float g_ffn[(size_t)Mrows * DFFd];
__device__ float g_att[(size_t)Bn * NHd * Nn * Nn];  // 33.5M
__device__ float g_D  [(size_t)Bn * Nn * Nn];        // 4.2M
__device__ float g_sq [Mrows];

// ---------------- reductions ----------------
__device__ __forceinline__ float blockmax256(float v) {
    __shared__ float red[8];
    #pragma unroll
    for (int o = 16; o > 0; o >>= 1) v = fmaxf(v, __shfl_xor_sync(0xffffffffu, v, o));
    if ((threadIdx.x & 31) == 0) red[threadIdx.x >> 5] = v;
    __syncthreads();
    float m = red[0];
    #pragma unroll
    for (int i = 1; i < 8; i++) m = fmaxf(m, red[i]);
    __syncthreads();
    return m;
}

__device__ __forceinline__ float blocksum256(float v) {
    __shared__ float red[8];
    #pragma unroll
    for (int o = 16; o > 0; o >>= 1) v += __shfl_xor_sync(0xffffffffu, v, o);
    if ((threadIdx.x & 31) == 0) red[threadIdx.x >> 5] = v;
    __syncthreads();
    float s = red[0];
    #pragma unroll
    for (int i = 1; i < 8; i++) s += red[i];
    __syncthreads();
    return s;
}

__device__ __forceinline__ float blocksum128(float v) {
    __shared__ float red[4];
    #pragma unroll
    for (int o = 16; o > 0; o >>= 1) v += __shfl_xor_sync(0xffffffffu, v, o);
    if ((threadIdx.x & 31) == 0) red[threadIdx.x >> 5] = v;
    __syncthreads();
    float s = red[0] + red[1] + red[2] + red[3];
    __syncthreads();
    return s;
}

// ---------------- concat [x | e_flat] ----------------
__global__ void cat_kernel(const float* __restrict__ x, const float* __restrict__ e) {
    size_t idx = (size_t)blockIdx.x * blockDim.x + threadIdx.x;
    if (idx >= (size_t)Mrows * KCAT) return;
    size_t r = idx / KCAT;
    int    c = (int)(idx - r * KCAT);
    float v;
    if (c < XDim) v = x[r * XDim + c];
    else          v = e[r * (size_t)EROW + (c - XDim)];
    g_cat[idx] = v;
}

// ---------------- generic SGEMM: C[M,Nc] = A[M,K] @ B[K,Nc] (+bias)(+relu) ----------------
__global__ __launch_bounds__(256) void gemm_kernel(
    const float* __restrict__ A, int lda,
    const float* __restrict__ Bm, int ldb,
    const float* __restrict__ bias,
    float* __restrict__ C, int ldc,
    int M, int Ncols, int K, int relu)
{
    __shared__ float As[16][64];
    __shared__ float Bs[16][64];
    int m0 = blockIdx.y * 64, n0 = blockIdx.x * 64;
    int t  = threadIdx.x;
    int tx = t & 15, ty = t >> 4;
    float acc[4][4];
    #pragma unroll
    for (int i = 0; i < 4; i++)
        #pragma unroll
        for (int j = 0; j < 4; j++) acc[i][j] = 0.f;

    int l  = t * 4;
    int ar = l >> 4, ac = l & 15;   // A tile: 64 rows x 16 k
    int br = l >> 6, bc = l & 63;   // B tile: 16 k  x 64 cols

    for (int k0 = 0; k0 < K; k0 += 16) {
        #pragma unroll
        for (int u = 0; u < 4; u++) {
            int kk = k0 + ac + u;
            As[ac + u][ar] = (kk < K) ? A[(size_t)(m0 + ar) * lda + kk] : 0.f;
        }
        {
            int kk = k0 + br;
            const float* bp = Bm + (size_t)kk * ldb + n0 + bc;
            bool ok = (kk < K);
            #pragma unroll
            for (int u = 0; u < 4; u++) Bs[br][bc + u] = ok ? bp[u] : 0.f;
        }
        __syncthreads();
        #pragma unroll
        for (int kk = 0; kk < 16; kk++) {
            float a[4], b[4];
            #pragma unroll
            for (int i = 0; i < 4; i++) a[i] = As[kk][ty * 4 + i];
            #pragma unroll
            for (int j = 0; j < 4; j++) b[j] = Bs[kk][tx * 4 + j];
            #pragma unroll
            for (int i = 0; i < 4; i++)
                #pragma unroll
                for (int j = 0; j < 4; j++) acc[i][j] = fmaf(a[i], b[j], acc[i][j]);
        }
        __syncthreads();
    }
    #pragma unroll
    for (int i = 0; i < 4; i++) {
        int gm = m0 + ty * 4 + i;
        #pragma unroll
        for (int j = 0; j < 4; j++) {
            int gn = n0 + tx * 4 + j;
            float vv = acc[i][j] + (bias ? bias[gn] : 0.f);
            if (relu) vv = fmaxf(vv, 0.f);
            C[(size_t)gm * ldc + gn] = vv;
        }
    }
}

// ---------------- row squared norms of z ----------------
__global__ void sqnorm_kernel() {
    int r = blockIdx.x;
    float s = 0.f;
    for (int c = threadIdx.x; c < Hd; c += 128) {
        float v = g_z[(size_t)r * Hd + c];
        s += v * v;
    }
    s = blocksum128(s);
    if (threadIdx.x == 0) g_sq[r] = s;
}

// ---------------- masked pairwise distance: g_D = cdist(z,z)*dm ----------------
__global__ __launch_bounds__(256) void dist_kernel(const float* __restrict__ mask) {
    int b  = blockIdx.z;
    int ti = blockIdx.y * 64, tj = blockIdx.x * 64;
    const float* zb = g_z + (size_t)b * Nn * Hd;
    __shared__ float Zi[16][64];
    __shared__ float Zj[16][64];
    int t = threadIdx.x, tx = t & 15, ty = t >> 4;
    float acc[4][4];
    #pragma unroll
    for (int i = 0; i < 4; i++)
        #pragma unroll
        for (int j = 0; j < 4; j++) acc[i][j] = 0.f;

    int l = t * 4, ar = l >> 4, ac = l & 15;
    for (int k0 = 0; k0 < Hd; k0 += 16) {
        #pragma unroll
        for (int u = 0; u < 4; u++) {
            Zi[ac + u][ar] = zb[(size_t)(ti + ar) * Hd + k0 + ac + u];
            Zj[ac + u][ar] = zb[(size_t)(tj + ar) * Hd + k0 + ac + u];
        }
        __syncthreads();
        #pragma unroll
        for (int kk = 0; kk < 16; kk++) {
            float a[4], bb[4];
            #pragma unroll
            for (int i = 0; i < 4; i++) a[i] = Zi[kk][ty * 4 + i];
            #pragma unroll
            for (int j = 0; j < 4; j++) bb[j] = Zj[kk][tx * 4 + j];
            #pragma unroll
            for (int i = 0; i < 4; i++)
                #pragma unroll
                for (int j = 0; j < 4; j++) acc[i][j] = fmaf(a[i], bb[j], acc[i][j]);
        }
        __syncthreads();
    }
    #pragma unroll
    for (int i = 0; i < 4; i++) {
        int gi = ti + ty * 4 + i;
        float sqi = g_sq[b * Nn + gi], mi = mask[b * Nn + gi];
        #pragma unroll
        for (int j = 0; j < 4; j++) {
            int gj = tj + tx * 4 + j;
            float d2 = sqi + g_sq[b * Nn + gj] - 2.f * acc[i][j];
            d2 = fmaxf(d2, 0.f);
            float d  = (d2 > 1e-12f) ? sqrtf(d2) : 0.f;
            float dm = mi * mask[b * Nn + gj];
            g_D[((size_t)b * Nn + gi) * Nn + gj] = d * dm;
        }
    }
}

// ---------------- bias: D = (rowmax - D) masked, diag 0 ----------------
__global__ void distbias_kernel(const float* __restrict__ mask) {
    int r = blockIdx.x;            // b*Nn + i
    int b = r / Nn, i = r - b * Nn;
    float* p = g_D + (size_t)r * Nn;
    int t = threadIdx.x;
    float v  = p[t];
    float bm = blockmax256(v);
    float dm = mask[r] * mask[b * Nn + t];
    p[t] = (t == i) ? 0.f : (bm - v) * dm;
}

// ---------------- scores = QK^T/sqrt(48) + D ----------------
__global__ __launch_bounds__(256) void qk_kernel() {
    int bh = blockIdx.z;
    int b  = bh / NHd, h = bh - b * NHd;
    int ti = blockIdx.y * 64, tj = blockIdx.x * 64;
    const float* qb = g_q + (size_t)b * Nn * Hd + h * DHd;
    const float* kb = g_k + (size_t)b * Nn * Hd + h * DHd;
    __shared__ float Qs[64][49];
    __shared__ float Ks[64][49];
    int t = threadIdx.x, tx = t & 15, ty = t >> 4;
    for (int l = t; l < 64 * 48; l += 256) {
        int r = l / 48, c = l - r * 48;
        Qs[r][c] = qb[(size_t)(ti + r) * Hd + c];
        Ks[r][c] = kb[(size_t)(tj + r) * Hd + c];
    }
    __syncthreads();
    float acc[4][4];
    #pragma unroll
    for (int i = 0; i < 4; i++)
        #pragma unroll
        for (int j = 0; j < 4; j++) acc[i][j] = 0.f;
    #pragma unroll 4
    for (int kk = 0; kk < 48; kk++) {
        float a[4], bb[4];
        #pragma unroll
        for (int i = 0; i < 4; i++) a[i] = Qs[ty * 4 + i][kk];
        #pragma unroll
        for (int j = 0; j < 4; j++) bb[j] = Ks[tx * 4 + j][kk];
        #pragma unroll
        for (int i = 0; i < 4; i++)
            #pragma unroll
            for (int j = 0; j < 4; j++) acc[i][j] = fmaf(a[i], bb[j], acc[i][j]);
    }
    const float scale = 0.144337567297406441f;  // 1/sqrt(48)
    #pragma unroll
    for (int i = 0; i < 4; i++) {
        int gi = ti + ty * 4 + i;
        #pragma unroll
        for (int j = 0; j < 4; j++) {
            int gj = tj + tx * 4 + j;
            g_att[((size_t)bh * Nn + gi) * Nn + gj] =
                acc[i][j] * scale + g_D[((size_t)b * Nn + gi) * Nn + gj];
        }
    }
}

// ---------------- softmax over last dim (rows of 256) ----------------
__global__ void softmax_kernel() {
    float* p = g_att + (size_t)blockIdx.x * Nn;
    int t = threadIdx.x;
    float v  = p[t];
    float bm = blockmax256(v);
    float e  = __expf(v - bm);
    float s  = blocksum256(e);
    p[t] = e / s;
}

// ---------------- y = attn @ V ----------------
__global__ __launch_bounds__(256) void attnv_kernel() {
    int bh = blockIdx.y;
    int b  = bh / NHd, h = bh - b * NHd;
    int ti = blockIdx.x * 64;
    const float* arow = g_att + (size_t)bh * Nn * Nn;
    const float* vb   = g_v + (size_t)b * Nn * Hd + h * DHd;
    __shared__ float As[64][65];
    __shared__ float Vs[64][49];
    int t = threadIdx.x, tx = t & 15, ty = t >> 4;
    float acc[4][3];
    #pragma unroll
    for (int i = 0; i < 4; i++)
        #pragma unroll
        for (int j = 0; j < 3; j++) acc[i][j] = 0.f;

    for (int j0 = 0; j0 < Nn; j0 += 64) {
        for (int l = t; l < 64 * 64; l += 256)
            As[l >> 6][l & 63] = arow[(size_t)(ti + (l >> 6)) * Nn + j0 + (l & 63)];
        for (int l = t; l < 64 * 48; l += 256) {
            int r = l / 48, c = l - r * 48;
            Vs[r][c] = vb[(size_t)(j0 + r) * Hd + c];
        }
        __syncthreads();
        #pragma unroll 4
        for (int kk = 0; kk < 64; kk++) {
            float a[4], bb[3];
            #pragma unroll
            for (int i = 0; i < 4; i++) a[i] = As[ty * 4 + i][kk];
            #pragma unroll
            for (int j = 0; j < 3; j++) bb[j] = Vs[kk][tx * 3 + j];
            #pragma unroll
            for (int i = 0; i < 4; i++)
                #pragma unroll
                for (int j = 0; j < 3; j++) acc[i][j] = fmaf(a[i], bb[j], acc[i][j]);
        }
        __syncthreads();
    }
    #pragma unroll
    for (int i = 0; i < 4; i++) {
        int gi = ti + ty * 4 + i;
        #pragma unroll
        for (int j = 0; j < 3; j++)
            g_y[((size_t)b * Nn + gi) * Hd + h * DHd + tx * 3 + j] = acc[i][j];
    }
}

// ---------------- out = LayerNorm(a + r) ----------------
__global__ void addln_kernel(const float* __restrict__ a, const float* __restrict__ r,
                             const float* __restrict__ g, const float* __restrict__ be,
                             float* __restrict__ out) {
    int row = blockIdx.x;
    int t = threadIdx.x;
    float vals[3];
    float s = 0.f;
    #pragma unroll
    for (int u = 0; u < 3; u++) {
        int c = t + u * 128;
        float v = a[(size_t)row * Hd + c] + r[(size_t)row * Hd + c];
        vals[u] = v;
        s += v;
    }
    float mu = blocksum128(s) * (1.f / Hd);
    float s2 = 0.f;
    #pragma unroll
    for (int u = 0; u < 3; u++) { float d = vals[u] - mu; s2 += d * d; }
    float var  = blocksum128(s2) * (1.f / Hd);
    float rstd = rsqrtf(var + 1e-5f);
    #pragma unroll
    for (int u = 0; u < 3; u++) {
        int c = t + u * 128;
        out[(size_t)row * Hd + c] = (vals[u] - mu) * rstd * g[c] + be[c];
    }
}

// ---------------- masked outputs ----------------
__global__ void out_x_kernel(const float* __restrict__ x, const float* __restrict__ mask,
                             float* __restrict__ out) {
    size_t idx = (size_t)blockIdx.x * blockDim.x + threadIdx.x;
    if (idx >= (size_t)Bn * Nn * XDim) return;
    out[idx] = x[idx] * mask[idx / XDim];
}
__global__ void out_e_kernel(const float* __restrict__ e, const float* __restrict__ mask,
                             float* __restrict__ out) {
    size_t idx = (size_t)blockIdx.x * blockDim.x + threadIdx.x;
    if (idx >= (size_t)Bn * Nn * Nn * EDim) return;
    size_t pair = idx / EDim;
    int j  = (int)(pair % Nn);
    size_t bi = pair / Nn;
    int b  = (int)(bi / Nn);
    out[idx] = e[idx] * mask[bi] * mask[(size_t)b * Nn + j];
}
__global__ void out_z_kernel(const float* __restrict__ mask, float* __restrict__ out) {
    size_t idx = (size_t)blockIdx.x * blockDim.x + threadIdx.x;
    if (idx >= (size_t)Mrows * Hd) return;
    out[idx] = g_z[idx] * mask[idx / Hd];
}

// ---------------- launcher ----------------
extern "C" void kernel_launch(void* const* d_in, const int* in_sizes, int n_in,
                              void* d_out, int out_size) {
    const float* x    = (const float*)d_in[0];
    const float* e    = (const float*)d_in[1];
    const float* mask = (const float*)d_in[2];
    const float* Wemb = (const float*)d_in[3];
    const float* Wq = (const float*)d_in[4];  const float* bq = (const float*)d_in[5];
    const float* Wk = (const float*)d_in[6];  const float* bk = (const float*)d_in[7];
    const float* Wv = (const float*)d_in[8];  const float* bv = (const float*)d_in[9];
    const float* Wo = (const float*)d_in[10]; const float* bo = (const float*)d_in[11];
    const float* g1 = (const float*)d_in[12]; const float* be1 = (const float*)d_in[13];
    const float* W1 = (const float*)d_in[14]; const float* b1  = (const float*)d_in[15];
    const float* W2 = (const float*)d_in[16]; const float* b2  = (const float*)d_in[17];
    const float* g2 = (const float*)d_in[18]; const float* be2 = (const float*)d_in[19];
    float* out = (float*)d_out;

    float *cat, *z, *q, *k, *v, *y, *x1, *ffn;
    cudaGetSymbolAddress((void**)&cat, g_cat);
    cudaGetSymbolAddress((void**)&z,   g_z);
    cudaGetSymbolAddress((void**)&q,   g_q);
    cudaGetSymbolAddress((void**)&k,   g_k);
    cudaGetSymbolAddress((void**)&v,   g_v);
    cudaGetSymbolAddress((void**)&y,   g_y);
    cudaGetSymbolAddress((void**)&x1,  g_x1);
    cudaGetSymbolAddress((void**)&ffn, g_ffn);

    // embedding
    {
        size_t tot = (size_t)Mrows * KCAT;
        cat_kernel<<<(unsigned)((tot + 255) / 256), 256>>>(x, e);
        gemm_kernel<<<dim3(Hd / 64, Mrows / 64), 256>>>(
            cat, KCAT, Wemb, Hd, nullptr, z, Hd, Mrows, Hd, KCAT, 0);
    }

    for (int l = 0; l < DEPTH; l++) {
        const size_t wofs = (size_t)l * Hd * Hd;
        // distance bias
        sqnorm_kernel<<<Mrows, 128>>>();
        dist_kernel<<<dim3(4, 4, Bn), 256>>>(mask);
        distbias_kernel<<<Mrows, 256>>>(mask);
        // QKV
        gemm_kernel<<<dim3(Hd / 64, Mrows / 64), 256>>>(
            z, Hd, Wq + wofs, Hd, bq + (size_t)l * Hd, q, Hd, Mrows, Hd, Hd, 0);
        gemm_kernel<<<dim3(Hd / 64, Mrows / 64), 256>>>(
            z, Hd, Wk + wofs, Hd, bk + (size_t)l * Hd, k, Hd, Mrows, Hd, Hd, 0);
        gemm_kernel<<<dim3(Hd / 64, Mrows / 64), 256>>>(
            z, Hd, Wv + wofs, Hd, bv + (size_t)l * Hd, v, Hd, Mrows, Hd, Hd, 0);
        // attention
        qk_kernel<<<dim3(4, 4, Bn * NHd), 256>>>();
        softmax_kernel<<<Bn * NHd * Nn, 256>>>();
        attnv_kernel<<<dim3(4, Bn * NHd), 256>>>();
        // output projection (into q as temp) + AddNorm
        gemm_kernel<<<dim3(Hd / 64, Mrows / 64), 256>>>(
            y, Hd, Wo + wofs, Hd, bo + (size_t)l * Hd, q, Hd, Mrows, Hd, Hd, 0);
        addln_kernel<<<Mrows, 128>>>(z, q, g1 + (size_t)l * Hd, be1 + (size_t)l * Hd, x1);
        // FFN
        gemm_kernel<<<dim3(DFFd / 64, Mrows / 64), 256>>>(
            x1, Hd, W1 + (size_t)l * Hd * DFFd, DFFd, b1 + (size_t)l * DFFd,
            ffn, DFFd, Mrows, DFFd, Hd, 1);
        gemm_kernel<<<dim3(Hd / 64, Mrows / 64), 256>>>(
            ffn, DFFd, W2 + (size_t)l * DFFd * Hd, Hd, b2 + (size_t)l * Hd,
            q, Hd, Mrows, Hd, DFFd, 0);
        addln_kernel<<<Mrows, 128>>>(x1, q, g2 + (size_t)l * Hd, be2 + (size_t)l * Hd, z);
    }

    // outputs: [X_out | E_out | z_out]
    const size_t XTOT = (size_t)Bn * Nn * XDim;       // 1,933,312
    const size_t ETOT = (size_t)Bn * Nn * Nn * EDim;  // 20,971,520
    const size_t ZTOT = (size_t)Mrows * Hd;           // 6,291,456
    out_x_kernel<<<(unsigned)((XTOT + 255) / 256), 256>>>(x, mask, out);
    out_e_kernel<<<(unsigned)((ETOT + 255) / 256), 256>>>(e, mask, out + XTOT);
    out_z_kernel<<<(unsigned)((ZTOT + 255) / 256), 256>>>(mask, out + XTOT + ETOT);
    (void)in_sizes; (void)n_in; (void)out_size;
}